// round 8
// baseline (speedup 1.0000x reference)
#include <cuda_runtime.h>

#define MNTH 512    // k_main threads: 2 groups x 256
#define TNTH 256    // k_tail threads
#define SB 32
#define BSZ 4096
#define ZSTR 34     // P1 / tail staging stride (32 cols)
#define ZS2 18      // per-group zin stride (16 cols + 2 pad)

// ---------------- shared layout (float offsets), main kernel ----------------
#define OFF_WS   0        // 32768 : weight tile up to 128x256 (shared)
#define OFF_PRE  32768    // 8192  : 2 groups x pre[16][256] (also P1 staging)
#define OFF_ZIN  40960    // 4608  : 2 groups x zin[128][ZS2]
#define OFF_CB   45568    // 4096  : 2 layers x 32 x 64 c-state
#define OFF_HB   49664    // 4096  : 2 layers x 32 x 64 h-final
#define OFF_BIAS 53760    // 256
#define OFF_GAM  54016    // 64
#define OFF_BET  54080    // 64
#define OFF_CTX  54144    // 768 ints
#define SMEM_MAIN (54912 * 4)

// tail shared layout (float offsets)
#define T_WS  0
#define T_ZIN 16384
#define T_TB  18560
#define SMEM_TAIL (18816 * 4)

#define TGRID 444
#define TMICRO 6144

__device__ float g_zbuf[12 * BSZ * 64];

typedef unsigned long long u64t;

__device__ __forceinline__ u64t pack2(float x) {
    u64t r; unsigned u = __float_as_uint(x);
    asm("mov.b64 %0, {%1, %1};" : "=l"(r) : "r"(u));
    return r;
}
__device__ __forceinline__ void fma2(u64t& a, u64t b, u64t c) {
    asm("fma.rn.f32x2 %0, %1, %2, %3;" : "=l"(a) : "l"(b), "l"(c), "l"(a));
}
__device__ __forceinline__ float2 unpack2(u64t v) {
    unsigned lo, hi;
    asm("mov.b64 {%0, %1}, %2;" : "=r"(lo), "=r"(hi) : "l"(v));
    return make_float2(__uint_as_float(lo), __uint_as_float(hi));
}
__device__ __forceinline__ float fsig(float x) { return __fdividef(1.0f, 1.0f + __expf(-x)); }
__device__ __forceinline__ float ftanh_(float x) { return 2.0f * __fdividef(1.0f, 1.0f + __expf(-2.0f * x)) - 1.0f; }
__device__ __forceinline__ void barg(int id) {        // per-group barrier, 256 thr
    asm volatile("bar.sync %0, %1;" :: "r"(id), "r"(256) : "memory");
}

// per-group transpose-stage of a 16x64 tile into zin rows [kbase, kbase+64)
__device__ __forceinline__ void stage_T16(float* __restrict__ zin, const float* __restrict__ src,
                                          int row_stride, int kbase, int gtid)
{
    int s  = gtid >> 4;
    int k4 = (gtid & 15) << 2;
    float4 v = *(const float4*)(src + s * row_stride + k4);
    zin[(kbase + k4 + 0) * ZS2 + s] = v.x;
    zin[(kbase + k4 + 1) * ZS2 + s] = v.y;
    zin[(kbase + k4 + 2) * ZS2 + s] = v.z;
    zin[(kbase + k4 + 3) * ZS2 + s] = v.w;
}

__device__ __forceinline__ void stage_w(float* dst, const float* src, int n_floats, int nth)
{
    const float4* s4 = (const float4*)src;
    float4* d4 = (float4*)dst;
    for (int i = threadIdx.x; i < (n_floats >> 2); i += nth) d4[i] = s4[i];
}

// One layer, 12 timesteps. Two 16-sample groups (8 warps = 2/SMSP each),
// phase-staggered so one group's GEMM overlaps the other's elementwise.
// K: 128 (zin=[z,h]) or 64 (zin=h). ZW: 0 none, 1 zbuf+=h, 2 zbuf=h.
template<int K, int ZW>
__device__ void cell_pass(float* __restrict__ sm, float* __restrict__ cbuf,
                          float* __restrict__ hbuf, int gb, int ctx_off,
                          const float* __restrict__ emb)
{
    const int tid   = threadIdx.x;
    const int g     = tid >> 8;          // group 0 / 1
    const int gtid  = tid & 255;
    const int ty3   = gtid >> 6;         // 0..3 -> 4 m-rows (2 pairs)
    const int tx    = gtid & 63;         // 0..63 -> 4 n-cols
    const int lane  = tid & 31;
    const int wid_l = gtid >> 5;         // 0..7 -> 2 samples each

    float*       Ws     = sm + OFF_WS;
    float*       pre    = sm + OFF_PRE + g * 4096;
    float*       zin    = sm + OFF_ZIN + g * 2304;
    const float* bias_s = sm + OFF_BIAS;
    const float* gam_s  = sm + OFF_GAM;
    const float* bet_s  = sm + OFF_BET;
    const int*   ctx_s  = (const int*)(sm + OFF_CTX);

    // prologue: stage initial h (transposed); for K=128 also z(t=0)
    stage_T16(zin, hbuf + (g << 4) * 64, 64, K - 64, gtid);
    if (K == 128)
        stage_T16(zin, g_zbuf + (size_t)(gb + (g << 4)) * 64, 64, 0, gtid);
    __syncthreads();

    if (g == 1) asm volatile("bar.sync 3, 512;" ::: "memory");   // stagger

    for (int t = 0; t < 12; t++) {
        // ---- GEMM: pre[m][n] = sum_k zin[k][m] * Ws[k][n], M=16 per group ----
        u64t acc[2][4];
        acc[0][0] = acc[0][1] = acc[0][2] = acc[0][3] = 0ull;
        acc[1][0] = acc[1][1] = acc[1][2] = acc[1][3] = 0ull;

        #pragma unroll 8
        for (int k = 0; k < K; k++) {
            const u64t* zp = (const u64t*)(zin + k * ZS2 + (ty3 << 2));
            u64t z0 = zp[0], z1 = zp[1];
            float4 w = *(const float4*)(Ws + (k << 8) + (tx << 2));
            u64t w0 = pack2(w.x), w1 = pack2(w.y), w2 = pack2(w.z), w3 = pack2(w.w);
            fma2(acc[0][0], z0, w0); fma2(acc[0][1], z0, w1); fma2(acc[0][2], z0, w2); fma2(acc[0][3], z0, w3);
            fma2(acc[1][0], z1, w0); fma2(acc[1][1], z1, w1); fma2(acc[1][2], z1, w2); fma2(acc[1][3], z1, w3);
        }

        if (g == 0 && t == 0) asm volatile("bar.arrive 3, 512;" ::: "memory");

        // ---- prefetch z(t+1) into registers (one float4 per thread) ----
        float4 zpf;
        int s0 = gtid >> 4, k40 = (gtid & 15) << 2;
        if (K == 128 && t < 11) {
            const float* srcz = g_zbuf + ((size_t)(t + 1) * BSZ + gb + (g << 4)) * 64;
            zpf = *(const float4*)(srcz + s0 * 64 + k40);
        }

        // ---- prefetch FiLM u for this timestep's 2 samples ----
        float ua[2][8], ub[2][8];
        #pragma unroll
        for (int mi = 0; mi < 2; mi++) {
            int ml = (wid_l << 1) + mi;
            int gs = (g << 4) + ml;
            const float* up = emb + ((size_t)ctx_s[gs * 24 + ctx_off + t] << 9);
            #pragma unroll
            for (int j = 0; j < 8; j++) {
                ua[mi][j] = up[lane + (j << 5)];
                ub[mi][j] = up[256 + lane + (j << 5)];
            }
        }

        // ---- write pre (+bias) ----
        float4 bv = *(const float4*)(bias_s + (tx << 2));
        #pragma unroll
        for (int p = 0; p < 2; p++) {
            float2 r0 = unpack2(acc[p][0]), r1 = unpack2(acc[p][1]);
            float2 r2 = unpack2(acc[p][2]), r3 = unpack2(acc[p][3]);
            int m0 = (ty3 << 2) + (p << 1);
            *(float4*)(pre + (m0 << 8) + (tx << 2)) =
                make_float4(r0.x + bv.x, r1.x + bv.y, r2.x + bv.z, r3.x + bv.w);
            *(float4*)(pre + ((m0 + 1) << 8) + (tx << 2)) =
                make_float4(r0.y + bv.x, r1.y + bv.y, r2.y + bv.z, r3.y + bv.w);
        }
        barg(1 + g);

        // ---- elementwise: warp handles 2 samples ----
        #pragma unroll
        for (int mi = 0; mi < 2; mi++) {
            int ml = (wid_l << 1) + mi;
            int gs = (g << 4) + ml;
            const float* pm = pre + (ml << 8);
            float v[8];
            #pragma unroll
            for (int j = 0; j < 8; j++) v[j] = pm[lane + (j << 5)];

            float mean[4], inv[4];
            #pragma unroll
            for (int g4 = 0; g4 < 4; g4++) {
                float s = v[2 * g4] + v[2 * g4 + 1];
                float q = v[2 * g4] * v[2 * g4] + v[2 * g4 + 1] * v[2 * g4 + 1];
                #pragma unroll
                for (int o = 16; o > 0; o >>= 1) {
                    s += __shfl_xor_sync(0xffffffffu, s, o);
                    q += __shfl_xor_sync(0xffffffffu, q, o);
                }
                float mu = s * 0.015625f;
                mean[g4] = mu;
                inv[g4]  = rsqrtf(fmaxf(q * 0.015625f - mu * mu, 0.0f) + 1e-5f);
            }

            float zf[8];
            #pragma unroll
            for (int j = 0; j < 8; j++) {
                int g4 = j >> 1;
                zf[j] = (v[j] - mean[g4]) * inv[g4] * (1.0f + ua[mi][j]) + ub[mi][j];
            }

            float* cm = cbuf + (gs << 6);
            float c0 = cm[lane], c1 = cm[lane + 32];
            float cn0 = fsig(zf[2]) * c0 + fsig(zf[0]) * ftanh_(zf[6]);
            float cn1 = fsig(zf[3]) * c1 + fsig(zf[1]) * ftanh_(zf[7]);

            float s = cn0 + cn1, q = cn0 * cn0 + cn1 * cn1;
            #pragma unroll
            for (int o = 16; o > 0; o >>= 1) {
                s += __shfl_xor_sync(0xffffffffu, s, o);
                q += __shfl_xor_sync(0xffffffffu, q, o);
            }
            float mu = s * 0.015625f;
            float rs = rsqrtf(fmaxf(q * 0.015625f - mu * mu, 0.0f) + 1e-5f);

            float hn0 = fsig(zf[4]) * ftanh_((cn0 - mu) * rs * gam_s[lane]      + bet_s[lane]);
            float hn1 = fsig(zf[5]) * ftanh_((cn1 - mu) * rs * gam_s[lane + 32] + bet_s[lane + 32]);

            cm[lane] = cn0; cm[lane + 32] = cn1;

            zin[(K - 64 + lane) * ZS2 + ml] = hn0;
            zin[(K - 32 + lane) * ZS2 + ml] = hn1;

            if (t == 11) {
                hbuf[(gs << 6) + lane]      = hn0;
                hbuf[(gs << 6) + lane + 32] = hn1;
            }

            if (ZW == 1) {
                float* zp = g_zbuf + ((size_t)t * BSZ + gb + gs) * 64;
                zp[lane]      += hn0;
                zp[lane + 32] += hn1;
            } else if (ZW == 2) {
                float* zp = g_zbuf + ((size_t)t * BSZ + gb + gs) * 64;
                zp[lane]      = hn0;
                zp[lane + 32] = hn1;
            }
        }

        // ---- commit z(t+1) into zin rows 0..63 ----
        if (K == 128 && t < 11) {
            zin[(k40 + 0) * ZS2 + s0] = zpf.x;
            zin[(k40 + 1) * ZS2 + s0] = zpf.y;
            zin[(k40 + 2) * ZS2 + s0] = zpf.z;
            zin[(k40 + 3) * ZS2 + s0] = zpf.w;
        }
        barg(1 + g);
    }
    __syncthreads();   // both groups done before Ws restage
}

extern "C" __global__ void __launch_bounds__(MNTH, 1)
k_main(const float* __restrict__ x, const int* __restrict__ context,
       const float* __restrict__ tlW, const float* __restrict__ tlb,
       const float* __restrict__ encW, const float* __restrict__ encb,
       const float* __restrict__ encg, const float* __restrict__ encbe,
       const float* __restrict__ dec0W, const float* __restrict__ dec0b,
       const float* __restrict__ dec0g, const float* __restrict__ dec0be,
       const float* __restrict__ decW, const float* __restrict__ decb,
       const float* __restrict__ decg, const float* __restrict__ decbe,
       const float* __restrict__ emb)
{
    extern __shared__ float sm[];
    const int tid = threadIdx.x;
    const int gb  = blockIdx.x * SB;
    float* zin_p = sm + OFF_PRE;   // P1 staging (stride ZSTR)
    float* Ws    = sm + OFF_WS;

    int* ctx_s = (int*)(sm + OFF_CTX);
    for (int i = tid; i < SB * 24; i += MNTH) ctx_s[i] = context[gb * 24 + i];
    for (int i = tid; i < 8192; i += MNTH) sm[OFF_CB + i] = 0.0f;
    stage_w(Ws, tlW, 4096, MNTH);
    for (int i = tid; i < 64; i += MNTH) sm[OFF_BIAS + i] = tlb[i];
    __syncthreads();

    // P1: z0[t][b] = x[b][t] @ tlW + tlb  (math on first 256 threads)
    {
        const int n4 = (tid & 15) << 2;
        const int mi = tid >> 4;
        for (int t = 0; t < 12; t++) {
            // stage x tile transposed (512 threads, one element pack each)
            {
                int i = tid;
                if (i < 512) {
                    int m  = i >> 4;
                    int k4 = (i & 15) << 2;
                    float4 v = *(const float4*)(x + (gb + m) * 768 + t * 64 + k4);
                    zin_p[(k4 + 0) * ZSTR + m] = v.x;
                    zin_p[(k4 + 1) * ZSTR + m] = v.y;
                    zin_p[(k4 + 2) * ZSTR + m] = v.z;
                    zin_p[(k4 + 3) * ZSTR + m] = v.w;
                }
            }
            __syncthreads();
            if (tid < 256) {
                u64t a0 = 0, a1 = 0, a2 = 0, a3 = 0;
                #pragma unroll 8
                for (int k = 0; k < 64; k++) {
                    const u64t* zp = (const u64t*)(zin_p + k * ZSTR + (mi << 1));
                    u64t zz = zp[0];
                    float4 w = *(const float4*)(Ws + (k << 6) + n4);
                    fma2(a0, zz, pack2(w.x));
                    fma2(a1, zz, pack2(w.y));
                    fma2(a2, zz, pack2(w.z));
                    fma2(a3, zz, pack2(w.w));
                }
                float4 bv = *(const float4*)(sm + OFF_BIAS + n4);
                float2 r0 = unpack2(a0), r1 = unpack2(a1), r2 = unpack2(a2), r3 = unpack2(a3);
                float* zp0 = g_zbuf + ((size_t)t * BSZ + gb + (mi << 1)) * 64 + n4;
                *(float4*)(zp0)      = make_float4(r0.x + bv.x, r1.x + bv.y, r2.x + bv.z, r3.x + bv.w);
                *(float4*)(zp0 + 64) = make_float4(r0.y + bv.x, r1.y + bv.y, r2.y + bv.z, r3.y + bv.w);
            }
            __syncthreads();
        }
    }

    float* cb0 = sm + OFF_CB;
    float* cb1 = sm + OFF_CB + 2048;
    float* hb0 = sm + OFF_HB;
    float* hb1 = sm + OFF_HB + 2048;

    // P2: encoder layer 0
    stage_w(Ws, encW, 32768, MNTH);
    stage_w(sm + OFF_BIAS, encb, 256, MNTH);
    for (int i = tid; i < 64; i += MNTH) { sm[OFF_GAM + i] = encg[i]; sm[OFF_BET + i] = encbe[i]; }
    __syncthreads();
    cell_pass<128, 1>(sm, cb0, hb0, gb, 0, emb);

    // P3: encoder layer 1
    stage_w(Ws, encW + 32768, 32768, MNTH);
    stage_w(sm + OFF_BIAS, encb + 256, 256, MNTH);
    for (int i = tid; i < 64; i += MNTH) { sm[OFF_GAM + i] = encg[64 + i]; sm[OFF_BET + i] = encbe[64 + i]; }
    __syncthreads();
    cell_pass<128, 0>(sm, cb1, hb1, gb, 0, emb);

    // P4: decoder layer 0
    stage_w(Ws, dec0W, 16384, MNTH);
    stage_w(sm + OFF_BIAS, dec0b, 256, MNTH);
    for (int i = tid; i < 64; i += MNTH) { sm[OFF_GAM + i] = dec0g[i]; sm[OFF_BET + i] = dec0be[i]; }
    __syncthreads();
    cell_pass<64, 2>(sm, cb0, hb0, gb, 12, emb);

    // P5: decoder layer 1
    stage_w(Ws, decW, 32768, MNTH);
    stage_w(sm + OFF_BIAS, decb, 256, MNTH);
    for (int i = tid; i < 64; i += MNTH) { sm[OFF_GAM + i] = decg[i]; sm[OFF_BET + i] = decbe[i]; }
    __syncthreads();
    cell_pass<128, 1>(sm, cb1, hb1, gb, 12, emb);
}

// ============================================================================
// k_tail: persistent single wave, 444 CTAs; z register-prefetched one micro ahead.
// ============================================================================
extern "C" __global__ void __launch_bounds__(TNTH, 3)
k_tail(const float* __restrict__ tailW, const float* __restrict__ tailb,
       float* __restrict__ out)
{
    extern __shared__ float sm[];
    float* Ws  = sm + T_WS;
    float* zin = sm + T_ZIN;
    float* tb  = sm + T_TB;
    const int tid = threadIdx.x;
    const int ty  = tid >> 6;
    const int tx  = tid & 63;

    const int p      = blockIdx.x;
    const int mstart = (p * TMICRO) / TGRID;
    const int mend   = ((p + 1) * TMICRO) / TGRID;
    int cur = -1;

    const int m0s = tid >> 4, k40 = (tid & 15) << 2;
    const int i1 = tid + 256;
    const int m1s = i1 >> 4, k41 = (i1 & 15) << 2;

    float4 pf0, pf1;
    {
        int t0 = mstart % 12, job = mstart / 12, bt = job & 127;
        const float* src = g_zbuf + ((size_t)t0 * BSZ + bt * SB) * 64;
        pf0 = *(const float4*)(src + m0s * 64 + k40);
        pf1 = *(const float4*)(src + m1s * 64 + k41);
    }

    for (int mi = mstart; mi < mend; mi++) {
        const int t     = mi % 12;
        const int job   = mi / 12;
        const int gb    = (job & 127) * SB;
        const int ch    = job >> 7;

        if (ch != cur) {
            for (int i = tid; i < 16384; i += TNTH) {
                int k = i >> 8, n = i & 255;
                Ws[i] = tailW[((ch << 2) + (n >> 6)) * 4096 + (k << 6) + (n & 63)];
            }
            for (int i = tid; i < 256; i += TNTH)
                tb[i] = tailb[((ch << 2) + (i >> 6)) * 64 + (i & 63)];
            cur = ch;
        }

        zin[(k40 + 0) * ZSTR + m0s] = pf0.x;
        zin[(k40 + 1) * ZSTR + m0s] = pf0.y;
        zin[(k40 + 2) * ZSTR + m0s] = pf0.z;
        zin[(k40 + 3) * ZSTR + m0s] = pf0.w;
        zin[(k41 + 0) * ZSTR + m1s] = pf1.x;
        zin[(k41 + 1) * ZSTR + m1s] = pf1.y;
        zin[(k41 + 2) * ZSTR + m1s] = pf1.z;
        zin[(k41 + 3) * ZSTR + m1s] = pf1.w;

        if (mi + 1 < mend) {
            int tn = (mi + 1) % 12, jn = (mi + 1) / 12, btn = jn & 127;
            const float* src = g_zbuf + ((size_t)tn * BSZ + btn * SB) * 64;
            pf0 = *(const float4*)(src + m0s * 64 + k40);
            pf1 = *(const float4*)(src + m1s * 64 + k41);
        }
        __syncthreads();

        u64t acc[4][4];
        #pragma unroll
        for (int q = 0; q < 4; q++)
            acc[q][0] = acc[q][1] = acc[q][2] = acc[q][3] = 0ull;

        #pragma unroll 8
        for (int k = 0; k < 64; k++) {
            const u64t* zp = (const u64t*)(zin + k * ZSTR + (ty << 3));
            u64t z0 = zp[0], z1 = zp[1], z2 = zp[2], z3 = zp[3];
            float4 w = *(const float4*)(Ws + (k << 8) + (tx << 2));
            u64t w0 = pack2(w.x), w1 = pack2(w.y), w2 = pack2(w.z), w3 = pack2(w.w);
            fma2(acc[0][0], z0, w0); fma2(acc[0][1], z0, w1); fma2(acc[0][2], z0, w2); fma2(acc[0][3], z0, w3);
            fma2(acc[1][0], z1, w0); fma2(acc[1][1], z1, w1); fma2(acc[1][2], z1, w2); fma2(acc[1][3], z1, w3);
            fma2(acc[2][0], z2, w0); fma2(acc[2][1], z2, w1); fma2(acc[2][2], z2, w2); fma2(acc[2][3], z2, w3);
            fma2(acc[3][0], z3, w0); fma2(acc[3][1], z3, w1); fma2(acc[3][2], z3, w2); fma2(acc[3][3], z3, w3);
        }

        float4 bv = *(const float4*)(tb + (tx << 2));
        int nt = (cur << 2) + (tx >> 4);
        int d  = (tx << 2) & 63;
        #pragma unroll
        for (int q = 0; q < 4; q++) {
            float2 r0 = unpack2(acc[q][0]), r1 = unpack2(acc[q][1]);
            float2 r2 = unpack2(acc[q][2]), r3 = unpack2(acc[q][3]);
            int mm = (ty << 3) + (q << 1);
            float* op = out + (size_t)(gb + mm) * 12288 + nt * 768 + t * 64 + d;
            *(float4*)(op)         = make_float4(r0.x + bv.x, r1.x + bv.y, r2.x + bv.z, r3.x + bv.w);
            *(float4*)(op + 12288) = make_float4(r0.y + bv.x, r1.y + bv.y, r2.y + bv.z, r3.y + bv.w);
        }
        __syncthreads();
    }
}

extern "C" void kernel_launch(void* const* d_in, const int* in_sizes, int n_in,
                              void* d_out, int out_size)
{
    cudaFuncSetAttribute(k_main, cudaFuncAttributeMaxDynamicSharedMemorySize, SMEM_MAIN);
    cudaFuncSetAttribute(k_tail, cudaFuncAttributeMaxDynamicSharedMemorySize, SMEM_TAIL);

    k_main<<<BSZ / SB, MNTH, SMEM_MAIN>>>(
        (const float*)d_in[0],  (const int*)d_in[1],
        (const float*)d_in[2],  (const float*)d_in[3],
        (const float*)d_in[4],  (const float*)d_in[5],
        (const float*)d_in[6],  (const float*)d_in[7],
        (const float*)d_in[8],  (const float*)d_in[9],
        (const float*)d_in[10], (const float*)d_in[11],
        (const float*)d_in[12], (const float*)d_in[13],
        (const float*)d_in[14], (const float*)d_in[15],
        (const float*)d_in[18]);

    k_tail<<<TGRID, TNTH, SMEM_TAIL>>>(
        (const float*)d_in[16], (const float*)d_in[17], (float*)d_out);
}

// round 9
// speedup vs baseline: 1.0461x; 1.0461x over previous
#include <cuda_runtime.h>

#define NTH 256
#define SBM 28          // samples per main CTA
#define NBLK 147        // ceil(4096/28)
#define TNTH 256
#define SB 32           // tail batch tile
#define BSZ 4096
#define ZSTR 34

// ---------------- shared layout (float offsets), main kernel ----------------
#define OFF_WS   0        // 32768 : weight tile up to 128x256
#define OFF_PRE  32768    // 8192  : pre[32][256] (also P1 staging)
#define OFF_ZIN  40960    // 4608  : zin[128][ZSTR]
#define OFF_CB   45568    // 4096  : 2 layers x 32 x 64 c-state
#define OFF_HB   49664    // 4096  : 2 layers x 32 x 64 h-final
#define OFF_BIAS 53760    // 256
#define OFF_GAM  54016    // 64
#define OFF_BET  54080    // 64
#define OFF_CTX  54144    // 768 ints
#define SMEM_MAIN (54912 * 4)

// tail shared layout (float offsets)
#define T_WS  0
#define T_ZIN 16384
#define T_TB  18560
#define SMEM_TAIL (18816 * 4)

#define TGRID 444
#define TMICRO 6144

__device__ float g_zbuf[12 * BSZ * 64];

typedef unsigned long long u64t;

__device__ __forceinline__ u64t pack2(float x) {
    u64t r; unsigned u = __float_as_uint(x);
    asm("mov.b64 %0, {%1, %1};" : "=l"(r) : "r"(u));
    return r;
}
__device__ __forceinline__ void fma2(u64t& a, u64t b, u64t c) {
    asm("fma.rn.f32x2 %0, %1, %2, %3;" : "=l"(a) : "l"(b), "l"(c), "l"(a));
}
__device__ __forceinline__ float2 unpack2(u64t v) {
    unsigned lo, hi;
    asm("mov.b64 {%0, %1}, %2;" : "=r"(lo), "=r"(hi) : "l"(v));
    return make_float2(__uint_as_float(lo), __uint_as_float(hi));
}
__device__ __forceinline__ float fsig(float x) { return __fdividef(1.0f, 1.0f + __expf(-x)); }
__device__ __forceinline__ float ftanh_(float x) { return 2.0f * __fdividef(1.0f, 1.0f + __expf(-2.0f * x)) - 1.0f; }

// variable-M transpose-stage: zin[(kbase+k)*ZSTR + m] = src[m*row_stride + k], m<M
__device__ __forceinline__ void stage_TM(float* __restrict__ zin, const float* __restrict__ src,
                                         int row_stride, int kbase, int M)
{
    for (int i = threadIdx.x; i < M * 16; i += NTH) {
        int m  = i >> 4;
        int k4 = (i & 15) << 2;
        float4 v = *(const float4*)(src + m * row_stride + k4);
        zin[(kbase + k4 + 0) * ZSTR + m] = v.x;
        zin[(kbase + k4 + 1) * ZSTR + m] = v.y;
        zin[(kbase + k4 + 2) * ZSTR + m] = v.z;
        zin[(kbase + k4 + 3) * ZSTR + m] = v.w;
    }
}

__device__ __forceinline__ void stage_w(float* dst, const float* src, int n_floats)
{
    const float4* s4 = (const float4*)src;
    float4* d4 = (float4*)dst;
    for (int i = threadIdx.x; i < (n_floats >> 2); i += NTH) d4[i] = s4[i];
}

// GEMM inner loop: PC pair-slots, pairs p = ty + 4*pp (interleaved for SMSP balance)
template<int K, int PC>
__device__ __forceinline__ void gemm_k(const float* __restrict__ zin,
                                       const float* __restrict__ Ws,
                                       int ty, int tx, u64t (&acc)[4][4])
{
    #pragma unroll 8
    for (int k = 0; k < K; k++) {
        float4 w = *(const float4*)(Ws + (k << 8) + (tx << 2));
        u64t w0 = pack2(w.x), w1 = pack2(w.y), w2 = pack2(w.z), w3 = pack2(w.w);
        #pragma unroll
        for (int pp = 0; pp < PC; pp++) {
            u64t z = *(const u64t*)(zin + k * ZSTR + ((ty + (pp << 2)) << 1));
            fma2(acc[pp][0], z, w0); fma2(acc[pp][1], z, w1);
            fma2(acc[pp][2], z, w2); fma2(acc[pp][3], z, w3);
        }
    }
}
// generic fallback (tail CTA only)
template<int K>
__device__ __forceinline__ void gemm_kv(const float* __restrict__ zin,
                                        const float* __restrict__ Ws,
                                        int ty, int tx, int pc, u64t (&acc)[4][4])
{
    for (int k = 0; k < K; k++) {
        float4 w = *(const float4*)(Ws + (k << 8) + (tx << 2));
        u64t w0 = pack2(w.x), w1 = pack2(w.y), w2 = pack2(w.z), w3 = pack2(w.w);
        for (int pp = 0; pp < pc; pp++) {
            u64t z = *(const u64t*)(zin + k * ZSTR + ((ty + (pp << 2)) << 1));
            fma2(acc[pp][0], z, w0); fma2(acc[pp][1], z, w1);
            fma2(acc[pp][2], z, w2); fma2(acc[pp][3], z, w3);
        }
    }
}

// One layer, 12 timesteps, M samples (M even, <=32). Pipelined single group.
// K: 128 (zin=[z,h]) or 64 (zin=h). ZW: 0 none, 1 zbuf+=h, 2 zbuf=h.
template<int K, int ZW>
__device__ void cell_pass(float* __restrict__ sm, float* __restrict__ cbuf,
                          float* __restrict__ hbuf, int gb, int M, int ctx_off,
                          const float* __restrict__ emb)
{
    float*       Ws     = sm + OFF_WS;
    float*       pre    = sm + OFF_PRE;
    float*       zin    = sm + OFF_ZIN;
    const float* bias_s = sm + OFF_BIAS;
    const float* gam_s  = sm + OFF_GAM;
    const float* bet_s  = sm + OFF_BET;
    const int*   ctx_s  = (const int*)(sm + OFF_CTX);

    const int tid  = threadIdx.x;
    const int ty   = tid >> 6;
    const int tx   = tid & 63;
    const int lane = tid & 31;
    const int wid  = tid >> 5;

    const int npairs = M >> 1;
    int pc = (npairs - ty + 3) >> 2;
    if (pc < 0) pc = 0; if (pc > 4) pc = 4;

    // prologue: stage initial h (transposed); for K=128 also z(t=0)
    stage_TM(zin, hbuf, 64, K - 64, M);
    if (K == 128) stage_TM(zin, g_zbuf + (size_t)gb * 64, 64, 0, M);
    __syncthreads();

    for (int t = 0; t < 12; t++) {
        // ---- GEMM ----
        u64t acc[4][4];
        #pragma unroll
        for (int p = 0; p < 4; p++)
            acc[p][0] = acc[p][1] = acc[p][2] = acc[p][3] = 0ull;

        if (pc == 4)      gemm_k<K, 4>(zin, Ws, ty, tx, acc);
        else if (pc == 3) gemm_k<K, 3>(zin, Ws, ty, tx, acc);
        else if (pc > 0)  gemm_kv<K>(zin, Ws, ty, tx, pc, acc);

        // ---- prefetch z(t+1) into registers ----
        float4 zpf0, zpf1;
        bool v0 = false, v1 = false;
        if (K == 128 && t < 11) {
            const float* srcz = g_zbuf + ((size_t)(t + 1) * BSZ + gb) * 64;
            if (tid < M * 16) {
                zpf0 = *(const float4*)(srcz + (tid >> 4) * 64 + ((tid & 15) << 2));
                v0 = true;
            }
            int i1 = tid + 256;
            if (i1 < M * 16) {
                zpf1 = *(const float4*)(srcz + (i1 >> 4) * 64 + ((i1 & 15) << 2));
                v1 = true;
            }
        }

        // ---- prefetch FiLM u: samples s = mi*8 + wid (balanced across SMSPs) ----
        float ua[4][8], ub[4][8];
        #pragma unroll
        for (int mi = 0; mi < 4; mi++) {
            int s = (mi << 3) + wid;
            if (s < M) {
                const float* up = emb + ((size_t)ctx_s[s * 24 + ctx_off + t] << 9);
                #pragma unroll
                for (int j = 0; j < 8; j++) {
                    ua[mi][j] = up[lane + (j << 5)];
                    ub[mi][j] = up[256 + lane + (j << 5)];
                }
            }
        }

        // ---- write pre (+bias) ----
        float4 bv = *(const float4*)(bias_s + (tx << 2));
        #pragma unroll
        for (int pp = 0; pp < 4; pp++) {
            if (pp >= pc) break;
            float2 r0 = unpack2(acc[pp][0]), r1 = unpack2(acc[pp][1]);
            float2 r2 = unpack2(acc[pp][2]), r3 = unpack2(acc[pp][3]);
            int m0 = (ty + (pp << 2)) << 1;
            *(float4*)(pre + (m0 << 8) + (tx << 2)) =
                make_float4(r0.x + bv.x, r1.x + bv.y, r2.x + bv.z, r3.x + bv.w);
            *(float4*)(pre + ((m0 + 1) << 8) + (tx << 2)) =
                make_float4(r0.y + bv.x, r1.y + bv.y, r2.y + bv.z, r3.y + bv.w);
        }
        __syncthreads();

        // ---- elementwise: sample s = mi*8 + wid ----
        #pragma unroll
        for (int mi = 0; mi < 4; mi++) {
            int s = (mi << 3) + wid;
            if (s >= M) break;
            const float* pm = pre + (s << 8);
            float v[8];
            #pragma unroll
            for (int j = 0; j < 8; j++) v[j] = pm[lane + (j << 5)];

            float mean[4], inv[4];
            #pragma unroll
            for (int g4 = 0; g4 < 4; g4++) {
                float ss = v[2 * g4] + v[2 * g4 + 1];
                float q  = v[2 * g4] * v[2 * g4] + v[2 * g4 + 1] * v[2 * g4 + 1];
                #pragma unroll
                for (int o = 16; o > 0; o >>= 1) {
                    ss += __shfl_xor_sync(0xffffffffu, ss, o);
                    q  += __shfl_xor_sync(0xffffffffu, q, o);
                }
                float mu = ss * 0.015625f;
                mean[g4] = mu;
                inv[g4]  = rsqrtf(fmaxf(q * 0.015625f - mu * mu, 0.0f) + 1e-5f);
            }

            float zf[8];
            #pragma unroll
            for (int j = 0; j < 8; j++) {
                int g4 = j >> 1;
                zf[j] = (v[j] - mean[g4]) * inv[g4] * (1.0f + ua[mi][j]) + ub[mi][j];
            }

            float* cm = cbuf + (s << 6);
            float c0 = cm[lane], c1 = cm[lane + 32];
            float cn0 = fsig(zf[2]) * c0 + fsig(zf[0]) * ftanh_(zf[6]);
            float cn1 = fsig(zf[3]) * c1 + fsig(zf[1]) * ftanh_(zf[7]);

            float ss = cn0 + cn1, q = cn0 * cn0 + cn1 * cn1;
            #pragma unroll
            for (int o = 16; o > 0; o >>= 1) {
                ss += __shfl_xor_sync(0xffffffffu, ss, o);
                q  += __shfl_xor_sync(0xffffffffu, q, o);
            }
            float mu = ss * 0.015625f;
            float rs = rsqrtf(fmaxf(q * 0.015625f - mu * mu, 0.0f) + 1e-5f);

            float hn0 = fsig(zf[4]) * ftanh_((cn0 - mu) * rs * gam_s[lane]      + bet_s[lane]);
            float hn1 = fsig(zf[5]) * ftanh_((cn1 - mu) * rs * gam_s[lane + 32] + bet_s[lane + 32]);

            cm[lane] = cn0; cm[lane + 32] = cn1;

            zin[(K - 64 + lane) * ZSTR + s] = hn0;
            zin[(K - 32 + lane) * ZSTR + s] = hn1;

            if (t == 11) {
                hbuf[(s << 6) + lane]      = hn0;
                hbuf[(s << 6) + lane + 32] = hn1;
            }

            if (ZW == 1) {
                float* zp = g_zbuf + ((size_t)t * BSZ + gb + s) * 64;
                zp[lane]      += hn0;
                zp[lane + 32] += hn1;
            } else if (ZW == 2) {
                float* zp = g_zbuf + ((size_t)t * BSZ + gb + s) * 64;
                zp[lane]      = hn0;
                zp[lane + 32] = hn1;
            }
        }

        // ---- commit z(t+1) into zin rows 0..63 ----
        if (K == 128 && t < 11) {
            if (v0) {
                int m0 = tid >> 4, k40 = (tid & 15) << 2;
                zin[(k40 + 0) * ZSTR + m0] = zpf0.x;
                zin[(k40 + 1) * ZSTR + m0] = zpf0.y;
                zin[(k40 + 2) * ZSTR + m0] = zpf0.z;
                zin[(k40 + 3) * ZSTR + m0] = zpf0.w;
            }
            if (v1) {
                int i1 = tid + 256;
                int m1 = i1 >> 4, k41 = (i1 & 15) << 2;
                zin[(k41 + 0) * ZSTR + m1] = zpf1.x;
                zin[(k41 + 1) * ZSTR + m1] = zpf1.y;
                zin[(k41 + 2) * ZSTR + m1] = zpf1.z;
                zin[(k41 + 3) * ZSTR + m1] = zpf1.w;
            }
        }
        __syncthreads();
    }
}

extern "C" __global__ void __launch_bounds__(NTH, 1)
k_main(const float* __restrict__ x, const int* __restrict__ context,
       const float* __restrict__ tlW, const float* __restrict__ tlb,
       const float* __restrict__ encW, const float* __restrict__ encb,
       const float* __restrict__ encg, const float* __restrict__ encbe,
       const float* __restrict__ dec0W, const float* __restrict__ dec0b,
       const float* __restrict__ dec0g, const float* __restrict__ dec0be,
       const float* __restrict__ decW, const float* __restrict__ decb,
       const float* __restrict__ decg, const float* __restrict__ decbe,
       const float* __restrict__ emb)
{
    extern __shared__ float sm[];
    const int tid = threadIdx.x;
    const int gb  = blockIdx.x * SBM;
    const int M   = min(SBM, BSZ - gb);
    float* zin_p = sm + OFF_PRE;   // P1 staging (stride ZSTR)
    float* Ws    = sm + OFF_WS;

    int* ctx_s = (int*)(sm + OFF_CTX);
    for (int i = tid; i < M * 24; i += NTH) ctx_s[i] = context[gb * 24 + i];
    for (int i = tid; i < 8192; i += NTH) sm[OFF_CB + i] = 0.0f;
    stage_w(Ws, tlW, 4096);
    for (int i = tid; i < 64; i += NTH) sm[OFF_BIAS + i] = tlb[i];
    __syncthreads();

    // P1: z0[t][b] = x[b][t] @ tlW + tlb
    {
        const int n4 = (tid & 15) << 2;
        const int mi = tid >> 4;          // pair index 0..15
        const int npairs = M >> 1;
        for (int t = 0; t < 12; t++) {
            stage_TM(zin_p, x + (size_t)gb * 768 + t * 64, 768, 0, M);
            __syncthreads();
            u64t a0 = 0, a1 = 0, a2 = 0, a3 = 0;
            if (mi < npairs) {
                #pragma unroll 8
                for (int k = 0; k < 64; k++) {
                    const u64t* zp = (const u64t*)(zin_p + k * ZSTR + (mi << 1));
                    u64t zz = zp[0];
                    float4 w = *(const float4*)(Ws + (k << 6) + n4);
                    fma2(a0, zz, pack2(w.x));
                    fma2(a1, zz, pack2(w.y));
                    fma2(a2, zz, pack2(w.z));
                    fma2(a3, zz, pack2(w.w));
                }
                float4 bv = *(const float4*)(sm + OFF_BIAS + n4);
                float2 r0 = unpack2(a0), r1 = unpack2(a1), r2 = unpack2(a2), r3 = unpack2(a3);
                float* zp0 = g_zbuf + ((size_t)t * BSZ + gb + (mi << 1)) * 64 + n4;
                *(float4*)(zp0)      = make_float4(r0.x + bv.x, r1.x + bv.y, r2.x + bv.z, r3.x + bv.w);
                *(float4*)(zp0 + 64) = make_float4(r0.y + bv.x, r1.y + bv.y, r2.y + bv.z, r3.y + bv.w);
            }
            __syncthreads();
        }
    }

    float* cb0 = sm + OFF_CB;
    float* cb1 = sm + OFF_CB + 2048;
    float* hb0 = sm + OFF_HB;
    float* hb1 = sm + OFF_HB + 2048;

    // P2: encoder layer 0
    stage_w(Ws, encW, 32768);
    stage_w(sm + OFF_BIAS, encb, 256);
    for (int i = tid; i < 64; i += NTH) { sm[OFF_GAM + i] = encg[i]; sm[OFF_BET + i] = encbe[i]; }
    __syncthreads();
    cell_pass<128, 1>(sm, cb0, hb0, gb, M, 0, emb);

    // P3: encoder layer 1
    stage_w(Ws, encW + 32768, 32768);
    stage_w(sm + OFF_BIAS, encb + 256, 256);
    for (int i = tid; i < 64; i += NTH) { sm[OFF_GAM + i] = encg[64 + i]; sm[OFF_BET + i] = encbe[64 + i]; }
    __syncthreads();
    cell_pass<128, 0>(sm, cb1, hb1, gb, M, 0, emb);

    // P4: decoder layer 0
    stage_w(Ws, dec0W, 16384);
    stage_w(sm + OFF_BIAS, dec0b, 256);
    for (int i = tid; i < 64; i += NTH) { sm[OFF_GAM + i] = dec0g[i]; sm[OFF_BET + i] = dec0be[i]; }
    __syncthreads();
    cell_pass<64, 2>(sm, cb0, hb0, gb, M, 12, emb);

    // P5: decoder layer 1
    stage_w(Ws, decW, 32768);
    stage_w(sm + OFF_BIAS, decb, 256);
    for (int i = tid; i < 64; i += NTH) { sm[OFF_GAM + i] = decg[i]; sm[OFF_BET + i] = decbe[i]; }
    __syncthreads();
    cell_pass<128, 1>(sm, cb1, hb1, gb, M, 12, emb);
}

// ============================================================================
// k_tail: persistent single wave, 444 CTAs; z register-prefetched one micro ahead.
// ============================================================================
extern "C" __global__ void __launch_bounds__(TNTH, 3)
k_tail(const float* __restrict__ tailW, const float* __restrict__ tailb,
       float* __restrict__ out)
{
    extern __shared__ float sm[];
    float* Ws  = sm + T_WS;
    float* zin = sm + T_ZIN;
    float* tb  = sm + T_TB;
    const int tid = threadIdx.x;
    const int ty  = tid >> 6;
    const int tx  = tid & 63;

    const int p      = blockIdx.x;
    const int mstart = (p * TMICRO) / TGRID;
    const int mend   = ((p + 1) * TMICRO) / TGRID;
    int cur = -1;

    const int m0s = tid >> 4, k40 = (tid & 15) << 2;
    const int i1 = tid + 256;
    const int m1s = i1 >> 4, k41 = (i1 & 15) << 2;

    float4 pf0, pf1;
    {
        int t0 = mstart % 12, job = mstart / 12, bt = job & 127;
        const float* src = g_zbuf + ((size_t)t0 * BSZ + bt * SB) * 64;
        pf0 = *(const float4*)(src + m0s * 64 + k40);
        pf1 = *(const float4*)(src + m1s * 64 + k41);
    }

    for (int mi = mstart; mi < mend; mi++) {
        const int t     = mi % 12;
        const int job   = mi / 12;
        const int gb    = (job & 127) * SB;
        const int ch    = job >> 7;

        if (ch != cur) {
            for (int i = tid; i < 16384; i += TNTH) {
                int k = i >> 8, n = i & 255;
                Ws[i] = tailW[((ch << 2) + (n >> 6)) * 4096 + (k << 6) + (n & 63)];
            }
            for (int i = tid; i < 256; i += TNTH)
                tb[i] = tailb[((ch << 2) + (i >> 6)) * 64 + (i & 63)];
            cur = ch;
        }

        zin[(k40 + 0) * ZSTR + m0s] = pf0.x;
        zin[(k40 + 1) * ZSTR + m0s] = pf0.y;
        zin[(k40 + 2) * ZSTR + m0s] = pf0.z;
        zin[(k40 + 3) * ZSTR + m0s] = pf0.w;
        zin[(k41 + 0) * ZSTR + m1s] = pf1.x;
        zin[(k41 + 1) * ZSTR + m1s] = pf1.y;
        zin[(k41 + 2) * ZSTR + m1s] = pf1.z;
        zin[(k41 + 3) * ZSTR + m1s] = pf1.w;

        if (mi + 1 < mend) {
            int tn = (mi + 1) % 12, jn = (mi + 1) / 12, btn = jn & 127;
            const float* src = g_zbuf + ((size_t)tn * BSZ + btn * SB) * 64;
            pf0 = *(const float4*)(src + m0s * 64 + k40);
            pf1 = *(const float4*)(src + m1s * 64 + k41);
        }
        __syncthreads();

        u64t acc[4][4];
        #pragma unroll
        for (int q = 0; q < 4; q++)
            acc[q][0] = acc[q][1] = acc[q][2] = acc[q][3] = 0ull;

        #pragma unroll 8
        for (int k = 0; k < 64; k++) {
            const u64t* zp = (const u64t*)(zin + k * ZSTR + (ty << 3));
            u64t z0 = zp[0], z1 = zp[1], z2 = zp[2], z3 = zp[3];
            float4 w = *(const float4*)(Ws + (k << 8) + (tx << 2));
            u64t w0 = pack2(w.x), w1 = pack2(w.y), w2 = pack2(w.z), w3 = pack2(w.w);
            fma2(acc[0][0], z0, w0); fma2(acc[0][1], z0, w1); fma2(acc[0][2], z0, w2); fma2(acc[0][3], z0, w3);
            fma2(acc[1][0], z1, w0); fma2(acc[1][1], z1, w1); fma2(acc[1][2], z1, w2); fma2(acc[1][3], z1, w3);
            fma2(acc[2][0], z2, w0); fma2(acc[2][1], z2, w1); fma2(acc[2][2], z2, w2); fma2(acc[2][3], z2, w3);
            fma2(acc[3][0], z3, w0); fma2(acc[3][1], z3, w1); fma2(acc[3][2], z3, w2); fma2(acc[3][3], z3, w3);
        }

        float4 bv = *(const float4*)(tb + (tx << 2));
        int nt = (cur << 2) + (tx >> 4);
        int d  = (tx << 2) & 63;
        #pragma unroll
        for (int q = 0; q < 4; q++) {
            float2 r0 = unpack2(acc[q][0]), r1 = unpack2(acc[q][1]);
            float2 r2 = unpack2(acc[q][2]), r3 = unpack2(acc[q][3]);
            int mm = (ty << 3) + (q << 1);
            float* op = out + (size_t)(gb + mm) * 12288 + nt * 768 + t * 64 + d;
            *(float4*)(op)         = make_float4(r0.x + bv.x, r1.x + bv.y, r2.x + bv.z, r3.x + bv.w);
            *(float4*)(op + 12288) = make_float4(r0.y + bv.x, r1.y + bv.y, r2.y + bv.z, r3.y + bv.w);
        }
        __syncthreads();
    }
}

extern "C" void kernel_launch(void* const* d_in, const int* in_sizes, int n_in,
                              void* d_out, int out_size)
{
    cudaFuncSetAttribute(k_main, cudaFuncAttributeMaxDynamicSharedMemorySize, SMEM_MAIN);
    cudaFuncSetAttribute(k_tail, cudaFuncAttributeMaxDynamicSharedMemorySize, SMEM_TAIL);

    k_main<<<NBLK, NTH, SMEM_MAIN>>>(
        (const float*)d_in[0],  (const int*)d_in[1],
        (const float*)d_in[2],  (const float*)d_in[3],
        (const float*)d_in[4],  (const float*)d_in[5],
        (const float*)d_in[6],  (const float*)d_in[7],
        (const float*)d_in[8],  (const float*)d_in[9],
        (const float*)d_in[10], (const float*)d_in[11],
        (const float*)d_in[12], (const float*)d_in[13],
        (const float*)d_in[14], (const float*)d_in[15],
        (const float*)d_in[18]);

    k_tail<<<TGRID, TNTH, SMEM_TAIL>>>(
        (const float*)d_in[16], (const float*)d_in[17], (float*)d_out);
}